// round 12
// baseline (speedup 1.0000x reference)
#include <cuda_runtime.h>
#include <cuda_fp16.h>
#include <math.h>
#include <stdint.h>

#define N 4096
#define D 1024
#define OUTD 1000
#define KSEL 819
#define BN_EPS 1e-5f

// ---------------- scratch (device globals; no allocations allowed) ----------
__device__ float g_sq[N];
__device__ __half g_Fh[(size_t)N * D];     // fp16 hi of features
__device__ __half g_Fl[(size_t)N * D];     // fp16 lo residual
__device__ __half g_Wh[(size_t)1024 * 1024]; // W^T fp16 [n][k], n-padded
__device__ float g_thr[N];
__device__ float g_invd[N];
__device__ int   g_nnz[N];
__device__ int   g_lcnt[N];                // compact positive-list lengths
__device__ int   g_lcols[(size_t)N * N];   // positive entries of Ae rows
__device__ float g_lvals[(size_t)N * N];
__device__ int   g_cols2[(size_t)N * N];   // filtered mutual-kNN adjacency
__device__ float g_vals2[(size_t)N * N];
__device__ float g_S[(size_t)N * OUTD];
__device__ float g_t1[(size_t)N * OUTD];

// ---------------- baseline-PTX tensor-core helpers --------------------------
__device__ __forceinline__ uint32_t smem_u32(const void* p) {
    uint32_t a;
    asm("{ .reg .u64 t; cvta.to.shared.u64 t, %1; cvt.u32.u64 %0, t; }"
        : "=r"(a) : "l"(p));
    return a;
}
#define CP_ASYNC16(dst, src) \
    asm volatile("cp.async.cg.shared.global [%0], [%1], 16;" :: "r"(dst), "l"(src) : "memory")
#define CP_COMMIT() asm volatile("cp.async.commit_group;" ::: "memory")
#define CP_WAIT(n)  asm volatile("cp.async.wait_group %0;" :: "n"(n) : "memory")
#define LDMX4(r0, r1, r2, r3, addr) \
    asm volatile("ldmatrix.sync.aligned.m8n8.x4.shared.b16 {%0,%1,%2,%3}, [%4];" \
                 : "=r"(r0), "=r"(r1), "=r"(r2), "=r"(r3) : "r"(addr))
#define MMAF16(d, a, b0v, b1v) \
    asm volatile("mma.sync.aligned.m16n8k16.row.col.f32.f16.f16.f32 " \
                 "{%0,%1,%2,%3}, {%4,%5,%6,%7}, {%8,%9}, {%0,%1,%2,%3};" \
                 : "+f"((d)[0]), "+f"((d)[1]), "+f"((d)[2]), "+f"((d)[3]) \
                 : "r"((a)[0]), "r"((a)[1]), "r"((a)[2]), "r"((a)[3]), \
                   "r"(b0v), "r"(b1v))

// expf(-d2/9) underflows to exactly 0.0f for d2 >= 1000 (-d2/9 < -111)
#define D2_ZERO_CUT 1000.0f

// gram: KC=64 per barrier window (two serial 32-sub-chunks)
#define GKC 64
#define GNC (D / GKC)              // 16
#define GSAB 72                    // 64 + 8 pad fp16 -> 144 B row stride
#define GTILE_B (128 * GSAB * 2)   // 18432
#define GSTAGE_B (2 * GTILE_B)     // 36864; 2 stages = 73728
// support: KC=32, 3 tiles/stage (Ah, Al, Bh)
#define KC 32
#define NC (D / KC)
#define SAB 40
#define TILE_B (128 * SAB * 2)     // 10240
#define SSTAGE_B (3 * TILE_B)      // 30720; 2 stages = 61440
#define DUAL_SMEM 73728
#define NSUP 256                   // support CTAs first

// ---------------- prep kernels ----------------------------------------------
__global__ void prep_F(const float* __restrict__ F) {
    int row = blockIdx.x, tid = threadIdx.x;
    if (tid == 0) g_lcnt[row] = 0;
    float4 v = *(const float4*)(F + (size_t)row * D + tid * 4);
    float s = v.x * v.x + v.y * v.y + v.z * v.z + v.w * v.w;

    __half h0 = __float2half(v.x), h1 = __float2half(v.y);
    __half h2 = __float2half(v.z), h3 = __float2half(v.w);
    __half2 ph0, ph1, pl0, pl1;
    ph0.x = h0; ph0.y = h1; ph1.x = h2; ph1.y = h3;
    pl0.x = __float2half(v.x - __half2float(h0));
    pl0.y = __float2half(v.y - __half2float(h1));
    pl1.x = __float2half(v.z - __half2float(h2));
    pl1.y = __float2half(v.w - __half2float(h3));
    size_t o = (size_t)row * D + tid * 4;
    *(__half2*)(g_Fh + o)     = ph0;
    *(__half2*)(g_Fh + o + 2) = ph1;
    *(__half2*)(g_Fl + o)     = pl0;
    *(__half2*)(g_Fl + o + 2) = pl1;

    __shared__ float red[256];
    red[tid] = s; __syncthreads();
    for (int o2 = 128; o2 > 0; o2 >>= 1) {
        if (tid < o2) red[tid] += red[tid + o2];
        __syncthreads();
    }
    if (tid == 0) g_sq[row] = red[0];
}

// transpose W [k=1024][n=1000] -> Wh fp16 [n=1024 pad][k=1024]
__global__ void prep_W(const float* __restrict__ W) {
    __shared__ float t[32][33];
    int nx = blockIdx.x * 32 + threadIdx.x;
#pragma unroll
    for (int s = 0; s < 4; s++) {
        int k = blockIdx.y * 32 + threadIdx.y + s * 8;
        t[threadIdx.y + s * 8][threadIdx.x] =
            (nx < OUTD) ? W[(size_t)k * OUTD + nx] : 0.0f;
    }
    __syncthreads();
#pragma unroll
    for (int s = 0; s < 4; s++) {
        int n_ = blockIdx.x * 32 + threadIdx.y + s * 8;
        int k_ = blockIdx.y * 32 + threadIdx.x;
        g_Wh[(size_t)n_ * 1024 + k_] = __float2half(t[threadIdx.x][threadIdx.y + s * 8]);
    }
}

// ---------------- gram path: lower-tri tiles, KC=64, compact append ---------
__device__ __forceinline__ void gram_path(char* smem, int bid) {
    uint32_t sb = smem_u32(smem);
    int tid = threadIdx.x, wid = tid >> 5, lane = tid & 31;

    int tr = (int)((sqrtf(8.0f * (float)bid + 1.0f) - 1.0f) * 0.5f);
    while ((tr + 1) * (tr + 2) / 2 <= bid) tr++;
    while (tr * (tr + 1) / 2 > bid) tr--;
    int tc = bid - tr * (tr + 1) / 2;
    int row0 = tr * 128, col0 = tc * 128;

    const __half* Ag = g_Fh + (size_t)row0 * D;
    const __half* Bg = g_Fh + (size_t)col0 * D;

    float acc[2][8][4];
#pragma unroll
    for (int i = 0; i < 2; i++)
#pragma unroll
        for (int j = 0; j < 8; j++)
#pragma unroll
            for (int d = 0; d < 4; d++) acc[i][j][d] = 0.0f;

    int ldr = tid >> 1;                // row 0..127
    int lsb = (tid & 1) * 4;           // first of 4 16B segments

    auto issue = [&](int c) {
        if (c >= GNC) return;
        int s = c & 1;
        uint32_t dstA = sb + s * GSTAGE_B;
        uint32_t dstB = dstA + GTILE_B;
        int k0 = c * GKC;
#pragma unroll
        for (int q = 0; q < 4; q++) {
            int sg = lsb + q;
            uint32_t off = (uint32_t)ldr * (GSAB * 2) + sg * 16;
            CP_ASYNC16(dstA + off, (const void*)(Ag + (size_t)ldr * D + k0 + sg * 8));
            CP_ASYNC16(dstB + off, (const void*)(Bg + (size_t)ldr * D + k0 + sg * 8));
        }
        CP_COMMIT();
    };

    int wm = wid & 3, wn = wid >> 2;
    int a_row = (lane & 7) + ((lane >> 3) & 1) * 8;
    int a_col = ((lane >> 4) & 1) * 8;
    int b_row = (lane & 7) + ((lane >> 4) & 1) * 8;
    int b_col = ((lane >> 3) & 1) * 8;

    issue(0);
    for (int c = 0; c < GNC; c++) {
        CP_WAIT(0);
        __syncthreads();
        issue(c + 1);

        int s = c & 1;
        uint32_t Abase = sb + s * GSTAGE_B + (uint32_t)(wm * 32) * (GSAB * 2);
        uint32_t Bbase = sb + s * GSTAGE_B + GTILE_B + (uint32_t)(wn * 64) * (GSAB * 2);

#pragma unroll 1
        for (int sub = 0; sub < 2; sub++) {
            uint32_t kofs = (uint32_t)(sub * 32) * 2;
            // st-outer: 16 independent MMAs between any acc reuse
#pragma unroll
            for (int st = 0; st < 2; st++) {
                uint32_t a[2][4];
#pragma unroll
                for (int i = 0; i < 2; i++) {
                    uint32_t ad = Abase + (uint32_t)(i * 16 + a_row) * (GSAB * 2)
                                + kofs + (uint32_t)(st * 16 + a_col) * 2;
                    LDMX4(a[i][0], a[i][1], a[i][2], a[i][3], ad);
                }
                uint32_t b[4][4];
#pragma unroll
                for (int jp = 0; jp < 4; jp++) {
                    uint32_t bd = Bbase + (uint32_t)(jp * 16 + b_row) * (GSAB * 2)
                                + kofs + (uint32_t)(st * 16 + b_col) * 2;
                    LDMX4(b[jp][0], b[jp][1], b[jp][2], b[jp][3], bd);
                }
#pragma unroll
                for (int i = 0; i < 2; i++)
#pragma unroll
                    for (int j = 0; j < 8; j++) {
                        int jp = j >> 1, hf = (j & 1) * 2;
                        MMAF16(acc[i][j], a[i], b[jp][hf], b[jp][hf + 1]);
                    }
            }
        }
    }

    // epilogue: append positives to compact per-row lists (no dense store)
    int er = lane >> 2, ec = (lane & 3) * 2;
#pragma unroll
    for (int i = 0; i < 2; i++)
#pragma unroll
        for (int j = 0; j < 8; j++)
#pragma unroll
            for (int d = 0; d < 4; d++) {
                int r = row0 + wm * 32 + i * 16 + (d >> 1) * 8 + er;
                int cc = col0 + wn * 64 + j * 8 + ec + (d & 1);
                float d2 = fmaxf(g_sq[r] + g_sq[cc] - 2.0f * acc[i][j][d], 0.0f);
                if (d2 < D2_ZERO_CUT) {
                    float e = expf(-d2 / 9.0f);
                    if (e > 0.0f) {
                        int p = atomicAdd(&g_lcnt[r], 1);
                        g_lcols[(size_t)r * N + p] = cc;
                        g_lvals[(size_t)r * N + p] = e;
                        if (tr != tc) {
                            int p2 = atomicAdd(&g_lcnt[cc], 1);
                            g_lcols[(size_t)cc * N + p2] = r;
                            g_lvals[(size_t)cc * N + p2] = e;
                        }
                    }
                }
            }
}

// ---------------- support path: S = (Fh+Fl) @ Wh, fp16 2-term, 2-stage ------
__device__ __forceinline__ void support_path(char* smem, int sid) {
    uint32_t sb = smem_u32(smem);
    int tid = threadIdx.x, wid = tid >> 5, lane = tid & 31;
    int row0 = (sid >> 3) * 128, col0 = (sid & 7) * 128;

    float acc[2][8][4];
#pragma unroll
    for (int i = 0; i < 2; i++)
#pragma unroll
        for (int j = 0; j < 8; j++)
#pragma unroll
            for (int d = 0; d < 4; d++) acc[i][j][d] = 0.0f;

    int ldr = tid >> 2, lds = tid & 3;

    auto issue = [&](int c) {
        if (c >= NC) return;
        int s = c & 1;
        uint32_t st = sb + s * SSTAGE_B;
        int k0 = c * KC;
#pragma unroll
        for (int h = 0; h < 2; h++) {
            int r = ldr + h * 64;
            uint32_t off = (uint32_t)r * (SAB * 2) + lds * 16;
            CP_ASYNC16(st + off,              (const void*)(g_Fh + (size_t)(row0 + r) * D + k0 + lds * 8));
            CP_ASYNC16(st + TILE_B + off,     (const void*)(g_Fl + (size_t)(row0 + r) * D + k0 + lds * 8));
            CP_ASYNC16(st + 2 * TILE_B + off, (const void*)(g_Wh + (size_t)(col0 + r) * 1024 + k0 + lds * 8));
        }
        CP_COMMIT();
    };

    int wm = wid & 3, wn = wid >> 2;
    int a_row = (lane & 7) + ((lane >> 3) & 1) * 8;
    int a_col = ((lane >> 4) & 1) * 8;
    int b_row = (lane & 7) + ((lane >> 4) & 1) * 8;
    int b_col = ((lane >> 3) & 1) * 8;

    issue(0);
    for (int c = 0; c < NC; c++) {
        CP_WAIT(0);
        __syncthreads();
        issue(c + 1);

        int s = c & 1;
        uint32_t Ahb = sb + s * SSTAGE_B + (uint32_t)(wm * 32) * (SAB * 2);
        uint32_t Alb = Ahb + TILE_B;
        uint32_t Bhb = sb + s * SSTAGE_B + 2 * TILE_B + (uint32_t)(wn * 64) * (SAB * 2);

        // st-outer; within st: term-major (16 independent MMAs per term)
#pragma unroll
        for (int st = 0; st < 2; st++) {
            uint32_t ah[2][4], al[2][4];
#pragma unroll
            for (int i = 0; i < 2; i++) {
                uint32_t ro = (uint32_t)(i * 16 + a_row) * (SAB * 2)
                            + (uint32_t)(st * 16 + a_col) * 2;
                LDMX4(ah[i][0], ah[i][1], ah[i][2], ah[i][3], Ahb + ro);
                LDMX4(al[i][0], al[i][1], al[i][2], al[i][3], Alb + ro);
            }
            uint32_t bh[4][4];
#pragma unroll
            for (int jp = 0; jp < 4; jp++) {
                uint32_t ro = (uint32_t)(jp * 16 + b_row) * (SAB * 2)
                            + (uint32_t)(st * 16 + b_col) * 2;
                LDMX4(bh[jp][0], bh[jp][1], bh[jp][2], bh[jp][3], Bhb + ro);
            }
            // term 0: hi * W
#pragma unroll
            for (int i = 0; i < 2; i++)
#pragma unroll
                for (int j = 0; j < 8; j++) {
                    int jp = j >> 1, hf = (j & 1) * 2;
                    MMAF16(acc[i][j], ah[i], bh[jp][hf], bh[jp][hf + 1]);
                }
            // term 1: lo * W
#pragma unroll
            for (int i = 0; i < 2; i++)
#pragma unroll
                for (int j = 0; j < 8; j++) {
                    int jp = j >> 1, hf = (j & 1) * 2;
                    MMAF16(acc[i][j], al[i], bh[jp][hf], bh[jp][hf + 1]);
                }
        }
    }

    int er = lane >> 2, ec = (lane & 3) * 2;
#pragma unroll
    for (int i = 0; i < 2; i++)
#pragma unroll
        for (int j = 0; j < 8; j++)
#pragma unroll
            for (int dp = 0; dp < 2; dp++) {
                int r = row0 + wm * 32 + i * 16 + dp * 8 + er;
                int c = col0 + wn * 64 + j * 8 + ec;
                if (c < OUTD) {
                    float2 v = make_float2(acc[i][j][dp * 2], acc[i][j][dp * 2 + 1]);
                    *(float2*)(g_S + (size_t)r * OUTD + c) = v;
                }
            }
}

__global__ void __launch_bounds__(256, 2) dual_mma_kernel() {
    extern __shared__ char smem[];
    if (blockIdx.x < NSUP) support_path(smem, blockIdx.x);
    else                   gram_path(smem, blockIdx.x - NSUP);
}

// ---------------- per-row threshold: radix select over compact list ---------
__global__ void select_kernel() {
    int row = blockIdx.x;
    int L = g_lcnt[row];
    int tid = threadIdx.x, lane = tid & 31;
    if (L < KSEL) {               // K-th largest of the full row is a zero
        if (tid == 0) g_thr[row] = 0.0f;
        return;
    }
    __shared__ unsigned v[N];
    __shared__ int hist[256];
    __shared__ int sfx[256];
    __shared__ int s_bin, s_rem;
    for (int i = tid; i < L; i += 256)
        v[i] = __float_as_uint(g_lvals[(size_t)row * N + i]);
    __syncthreads();

    unsigned prefix = 0;
    int remaining = KSEL;
    for (int shift = 24; shift >= 0; shift -= 8) {
        hist[tid] = 0;
        __syncthreads();
        unsigned hm = (shift == 24) ? 0u : (0xFFFFFFFFu << (shift + 8));
        unsigned ph = prefix & hm;
        for (int i = tid; i < L; i += 256) {
            unsigned x = v[i];
            bool act = ((x & hm) == ph);
            int bin = (x >> shift) & 255;
            unsigned key = act ? (unsigned)bin : 0xFFFFFFFFu;
            unsigned mask = __match_any_sync(0xFFFFFFFFu, key);
            if (act && ((__ffs(mask) - 1) == lane))
                atomicAdd(&hist[bin], __popc(mask));
        }
        __syncthreads();
        sfx[tid] = hist[tid];
        __syncthreads();
        for (int off = 1; off < 256; off <<= 1) {
            int val = (tid + off < 256) ? sfx[tid + off] : 0;
            __syncthreads();
            sfx[tid] += val;
            __syncthreads();
        }
        int nb = (tid < 255) ? sfx[tid + 1] : 0;
        if (sfx[tid] >= remaining && nb < remaining) {
            s_bin = tid;
            s_rem = remaining - nb;
        }
        __syncthreads();
        prefix |= ((unsigned)s_bin) << shift;
        remaining = s_rem;
        __syncthreads();
    }
    if (tid == 0) g_thr[row] = __uint_as_float(prefix);
}

// ---------------- build mutual-kNN adjacency from compact lists -------------
__global__ void build_kernel() {
    int row = blockIdx.x, tid = threadIdx.x;
    int L = g_lcnt[row];
    if (L == 1) {                 // only the diagonal is positive
        if (tid == 0) { g_nnz[row] = 0; g_invd[row] = rsqrtf(2.0f); }
        return;
    }
    float ti = g_thr[row];
    __shared__ int s_n;
    __shared__ float red[256];
    if (tid == 0) s_n = 0;
    __syncthreads();
    float ls = 0.0f;
    for (int i = tid; i < L; i += 256) {
        int j = g_lcols[(size_t)row * N + i];
        float w = g_lvals[(size_t)row * N + i];
        if (j != row && w >= ti && w >= g_thr[j]) {
            int p = atomicAdd(&s_n, 1);
            g_cols2[(size_t)row * N + p] = j;
            g_vals2[(size_t)row * N + p] = w;
            ls += w;
        }
    }
    red[tid] = ls;
    __syncthreads();
    for (int o = 128; o > 0; o >>= 1) {
        if (tid < o) red[tid] += red[tid + o];
        __syncthreads();
    }
    if (tid == 0) {
        g_nnz[row] = s_n;
        g_invd[row] = rsqrtf(2.0f + red[0]);
    }
}

// ---------------- sparse propagation (scale fused on the fly) ---------------
__global__ void spmmA_kernel() {
    int row = blockIdx.x, tid = threadIdx.x;
    int nn = g_nnz[row];
    if (nn == 0) return;          // symmetric graph: nobody references this row
    float di = g_invd[row];
    float diag = di * di;
    const float* Xrow = g_S + (size_t)row * OUTD;
    int n0 = tid, n1 = tid + 256, n2 = tid + 512, n3 = tid + 768;
    float a0 = diag * Xrow[n0];
    float a1 = diag * Xrow[n1];
    float a2 = diag * Xrow[n2];
    float a3 = (n3 < OUTD) ? diag * Xrow[n3] : 0.0f;
    for (int e = 0; e < nn; e++) {
        int col = g_cols2[(size_t)row * N + e];
        float v = g_vals2[(size_t)row * N + e] * di * g_invd[col];
        const float* Xc = g_S + (size_t)col * OUTD;
        a0 += v * Xc[n0];
        a1 += v * Xc[n1];
        a2 += v * Xc[n2];
        if (n3 < OUTD) a3 += v * Xc[n3];
    }
    float* T = g_t1 + (size_t)row * OUTD;
    T[n0] = a0; T[n1] = a1; T[n2] = a2;
    if (n3 < OUTD) T[n3] = a3;
}

__global__ void spmmB_kernel(const float* __restrict__ bias,
                             const float* __restrict__ gamma,
                             const float* __restrict__ beta,
                             const float* __restrict__ mean,
                             const float* __restrict__ var,
                             const float* __restrict__ aifa1,
                             const float* __restrict__ aifa2,
                             const float* __restrict__ aifa3,
                             float* __restrict__ out) {
    int row = blockIdx.x, tid = threadIdx.x;
    int nn = g_nnz[row];
    float di = g_invd[row];
    float diag = di * di;
    float x0 = aifa1[0], x1 = aifa2[0], x2 = aifa3[0];
    float m = fmaxf(x0, fmaxf(x1, x2));
    float e0 = expf(x0 - m), e1 = expf(x1 - m), e2 = expf(x2 - m);
    float sden = e0 + e1 + e2;
    float c0 = e0 / sden, c1 = e1 / sden, c2 = e2 / sden;

    const float* Srow = g_S + (size_t)row * OUTD;
    float* Orow = out + (size_t)row * OUTD;

    if (nn == 0) {
#pragma unroll
        for (int q = 0; q < 4; q++) {
            int n = tid + q * 256;
            if (n < OUTD) {
                float s = Srow[n];
                float t = diag * s;
                float a = diag * t;
                float x = c0 * s + c1 * t + c2 * a + bias[n];
                float y = (x - mean[n]) * rsqrtf(var[n] + BN_EPS) * gamma[n] + beta[n];
                Orow[n] = fmaxf(y, 0.0f);
            }
        }
        return;
    }

    const float* Trow = g_t1 + (size_t)row * OUTD;
    int n0 = tid, n1 = tid + 256, n2 = tid + 512, n3 = tid + 768;
    float a0 = diag * Trow[n0];
    float a1 = diag * Trow[n1];
    float a2 = diag * Trow[n2];
    float a3 = (n3 < OUTD) ? diag * Trow[n3] : 0.0f;
    for (int e = 0; e < nn; e++) {
        int col = g_cols2[(size_t)row * N + e];
        float v = g_vals2[(size_t)row * N + e] * di * g_invd[col];
        const float* Xc = g_t1 + (size_t)col * OUTD;
        a0 += v * Xc[n0];
        a1 += v * Xc[n1];
        a2 += v * Xc[n2];
        if (n3 < OUTD) a3 += v * Xc[n3];
    }
    int ns[4] = {n0, n1, n2, n3};
    float as[4] = {a0, a1, a2, a3};
#pragma unroll
    for (int r = 0; r < 4; r++) {
        int n = ns[r];
        if (n < OUTD) {
            float x = c0 * Srow[n] + c1 * Trow[n] + c2 * as[r] + bias[n];
            float y = (x - mean[n]) * rsqrtf(var[n] + BN_EPS) * gamma[n] + beta[n];
            Orow[n] = fmaxf(y, 0.0f);
        }
    }
}

// ---------------- launch -----------------------------------------------------
extern "C" void kernel_launch(void* const* d_in, const int* in_sizes, int n_in,
                              void* d_out, int out_size) {
    const float* F     = (const float*)d_in[0];
    const float* W     = (const float*)d_in[1];
    const float* bias  = (const float*)d_in[2];
    const float* a1    = (const float*)d_in[3];
    const float* a2    = (const float*)d_in[4];
    const float* a3    = (const float*)d_in[5];
    const float* gamma = (const float*)d_in[6];
    const float* beta  = (const float*)d_in[7];
    const float* mean  = (const float*)d_in[8];
    const float* var   = (const float*)d_in[9];
    float* out = (float*)d_out;

    static int configured = -1;
    if (configured < 0) {
        cudaFuncSetAttribute(dual_mma_kernel,
                             cudaFuncAttributeMaxDynamicSharedMemorySize, DUAL_SMEM);
        configured = 1;
    }

    prep_F<<<N, 256>>>(F);
    prep_W<<<dim3(32, 32), dim3(32, 8)>>>(W);
    dual_mma_kernel<<<NSUP + 528, 256, DUAL_SMEM>>>();
    select_kernel<<<N, 256>>>();
    build_kernel<<<N, 256>>>();
    spmmA_kernel<<<N, 256>>>();
    spmmB_kernel<<<N, 256>>>(bias, gamma, beta, mean, var, a1, a2, a3, out);
}

// round 16
// speedup vs baseline: 1.5586x; 1.5586x over previous
#include <cuda_runtime.h>
#include <cuda_bf16.h>
#include <cuda_fp8.h>
#include <math.h>
#include <stdint.h>

#define N 4096
#define D 1024
#define OUTD 1000
#define KSEL 819
#define BN_EPS 1e-5f

// ---------------- scratch (device globals; no allocations allowed) ----------
__device__ float g_sq[N];
__device__ __nv_bfloat16 g_Fbf[(size_t)N * D];   // bf16 hi of features
__device__ __nv_bfloat16 g_Flo[(size_t)N * D];   // bf16 lo residual
__device__ uint8_t g_F8[(size_t)N * D];          // e4m3 features (gram only)
__device__ __nv_bfloat16 g_Wth[(size_t)1024 * 1024]; // W^T hi [n][k]
__device__ __nv_bfloat16 g_Wtl[(size_t)1024 * 1024]; // W^T lo
__device__ float g_thr[N];
__device__ float g_invd[N];
__device__ int   g_nnz[N];
__device__ int   g_lcnt[N];                // compact positive-list lengths
__device__ int   g_lcols[(size_t)N * N];   // positive entries of Ae rows
__device__ float g_lvals[(size_t)N * N];
__device__ int   g_cols2[(size_t)N * N];   // filtered mutual-kNN adjacency
__device__ float g_vals2[(size_t)N * N];
__device__ float g_S[(size_t)N * OUTD];
__device__ float g_t1[(size_t)N * OUTD];

// ---------------- baseline-PTX tensor-core helpers --------------------------
__device__ __forceinline__ uint32_t smem_u32(const void* p) {
    uint32_t a;
    asm("{ .reg .u64 t; cvta.to.shared.u64 t, %1; cvt.u32.u64 %0, t; }"
        : "=r"(a) : "l"(p));
    return a;
}
#define CP_ASYNC16(dst, src) \
    asm volatile("cp.async.cg.shared.global [%0], [%1], 16;" :: "r"(dst), "l"(src) : "memory")
#define CP_COMMIT() asm volatile("cp.async.commit_group;" ::: "memory")
#define CP_WAIT(n)  asm volatile("cp.async.wait_group %0;" :: "n"(n) : "memory")
#define LDMX4(r0, r1, r2, r3, addr) \
    asm volatile("ldmatrix.sync.aligned.m8n8.x4.shared.b16 {%0,%1,%2,%3}, [%4];" \
                 : "=r"(r0), "=r"(r1), "=r"(r2), "=r"(r3) : "r"(addr))
#define MMA16816(d, a, b0v, b1v) \
    asm volatile("mma.sync.aligned.m16n8k16.row.col.f32.bf16.bf16.f32 " \
                 "{%0,%1,%2,%3}, {%4,%5,%6,%7}, {%8,%9}, {%0,%1,%2,%3};" \
                 : "+f"((d)[0]), "+f"((d)[1]), "+f"((d)[2]), "+f"((d)[3]) \
                 : "r"((a)[0]), "r"((a)[1]), "r"((a)[2]), "r"((a)[3]), \
                   "r"(b0v), "r"(b1v))
// fp8 e4m3 MMA, K=32 per instruction (sm_89+ baseline PTX). Fragment byte
// layout == m16n8k16-b16 layout when fp8 pairs are viewed as u16, so the
// same ldmatrix.b16 staging works unchanged.
#define MMAE4M3(d, a, b0v, b1v) \
    asm volatile("mma.sync.aligned.m16n8k32.row.col.f32.e4m3.e4m3.f32 " \
                 "{%0,%1,%2,%3}, {%4,%5,%6,%7}, {%8,%9}, {%0,%1,%2,%3};" \
                 : "+f"((d)[0]), "+f"((d)[1]), "+f"((d)[2]), "+f"((d)[3]) \
                 : "r"((a)[0]), "r"((a)[1]), "r"((a)[2]), "r"((a)[3]), \
                   "r"(b0v), "r"(b1v))

// expf(-d2/9) underflows to exactly 0.0f for d2 >= 1000 (-d2/9 < -111)
#define D2_ZERO_CUT 1000.0f

// gram (fp8): rows of 512 u16 units; chunk = 64 u16 (=128 fp8) per stage
#define GD16 512                   // u16 units per row
#define GNC 8                      // 512 / 64
#define GSAB 72                    // 64 + 8 pad u16 -> 144 B row stride
#define GTILE_B (128 * GSAB * 2)   // 18432
#define GSTAGE_B (2 * GTILE_B)     // 36864; 2 stages = 73728
// support: bf16 split-2, KC=32, 4 tiles/stage
#define KC 32
#define NC (D / KC)
#define SAB 40
#define TILE_B (128 * SAB * 2)     // 10240
#define SSTAGE_B (4 * TILE_B)      // 40960; 2 stages = 81920
#define DUAL_SMEM 81920
#define NSUP 256                   // support CTAs first (heavier)

// ---------------- prep kernels ----------------------------------------------
__global__ void prep_F(const float* __restrict__ F) {
    int row = blockIdx.x, tid = threadIdx.x;
    if (tid == 0) g_lcnt[row] = 0;
    float4 v = *(const float4*)(F + (size_t)row * D + tid * 4);
    float s = v.x * v.x + v.y * v.y + v.z * v.z + v.w * v.w;

    __nv_bfloat16 h0 = __float2bfloat16(v.x), h1 = __float2bfloat16(v.y);
    __nv_bfloat16 h2 = __float2bfloat16(v.z), h3 = __float2bfloat16(v.w);
    __nv_bfloat162 ph0, ph1, pl0, pl1;
    ph0.x = h0; ph0.y = h1; ph1.x = h2; ph1.y = h3;
    pl0.x = __float2bfloat16(v.x - __bfloat162float(h0));
    pl0.y = __float2bfloat16(v.y - __bfloat162float(h1));
    pl1.x = __float2bfloat16(v.z - __bfloat162float(h2));
    pl1.y = __float2bfloat16(v.w - __bfloat162float(h3));
    size_t o = (size_t)row * D + tid * 4;
    *(__nv_bfloat162*)(g_Fbf + o)     = ph0;
    *(__nv_bfloat162*)(g_Fbf + o + 2) = ph1;
    *(__nv_bfloat162*)(g_Flo + o)     = pl0;
    *(__nv_bfloat162*)(g_Flo + o + 2) = pl1;

    // fp8 copy for the gram
    __nv_fp8_e4m3 q0(v.x), q1(v.y), q2(v.z), q3(v.w);
    uchar4 u;
    u.x = q0.__x; u.y = q1.__x; u.z = q2.__x; u.w = q3.__x;
    *(uchar4*)(g_F8 + o) = u;

    __shared__ float red[256];
    red[tid] = s; __syncthreads();
    for (int o2 = 128; o2 > 0; o2 >>= 1) {
        if (tid < o2) red[tid] += red[tid + o2];
        __syncthreads();
    }
    if (tid == 0) g_sq[row] = red[0];
}

// transpose W [k=1024][n=1000] -> Wt hi/lo bf16 [n=1024 pad][k=1024]
__global__ void prep_W(const float* __restrict__ W) {
    __shared__ float t[32][33];
    int nx = blockIdx.x * 32 + threadIdx.x;
#pragma unroll
    for (int s = 0; s < 4; s++) {
        int k = blockIdx.y * 32 + threadIdx.y + s * 8;
        t[threadIdx.y + s * 8][threadIdx.x] =
            (nx < OUTD) ? W[(size_t)k * OUTD + nx] : 0.0f;
    }
    __syncthreads();
#pragma unroll
    for (int s = 0; s < 4; s++) {
        int n_ = blockIdx.x * 32 + threadIdx.y + s * 8;
        int k_ = blockIdx.y * 32 + threadIdx.x;
        float w = t[threadIdx.x][threadIdx.y + s * 8];
        __nv_bfloat16 hi = __float2bfloat16(w);
        g_Wth[(size_t)n_ * 1024 + k_] = hi;
        g_Wtl[(size_t)n_ * 1024 + k_] = __float2bfloat16(w - __bfloat162float(hi));
    }
}

// ---------------- gram path: lower-tri tiles, fp8 e4m3, compact append ------
__device__ __forceinline__ void gram_path(char* smem, int bid) {
    uint32_t sb = smem_u32(smem);
    int tid = threadIdx.x, wid = tid >> 5, lane = tid & 31;

    int tr = (int)((sqrtf(8.0f * (float)bid + 1.0f) - 1.0f) * 0.5f);
    while ((tr + 1) * (tr + 2) / 2 <= bid) tr++;
    while (tr * (tr + 1) / 2 > bid) tr--;
    int tc = bid - tr * (tr + 1) / 2;
    int row0 = tr * 128, col0 = tc * 128;

    const uint16_t* Ag = (const uint16_t*)g_F8 + (size_t)row0 * GD16;
    const uint16_t* Bg = (const uint16_t*)g_F8 + (size_t)col0 * GD16;

    float acc[2][8][4];
#pragma unroll
    for (int i = 0; i < 2; i++)
#pragma unroll
        for (int j = 0; j < 8; j++)
#pragma unroll
            for (int d = 0; d < 4; d++) acc[i][j][d] = 0.0f;

    int ldr = tid >> 1;                // row 0..127
    int lsb = (tid & 1) * 4;           // first of 4 16B segments

    auto issue = [&](int c) {
        if (c >= GNC) return;
        int s = c & 1;
        uint32_t dstA = sb + s * GSTAGE_B;
        uint32_t dstB = dstA + GTILE_B;
        int k0 = c * 64;               // u16 units
#pragma unroll
        for (int q = 0; q < 4; q++) {
            int sg = lsb + q;
            uint32_t off = (uint32_t)ldr * (GSAB * 2) + sg * 16;
            CP_ASYNC16(dstA + off, (const void*)(Ag + (size_t)ldr * GD16 + k0 + sg * 8));
            CP_ASYNC16(dstB + off, (const void*)(Bg + (size_t)ldr * GD16 + k0 + sg * 8));
        }
        CP_COMMIT();
    };

    int wm = wid & 3, wn = wid >> 2;
    int a_row = (lane & 7) + ((lane >> 3) & 1) * 8;
    int a_col = ((lane >> 4) & 1) * 8;
    int b_row = (lane & 7) + ((lane >> 4) & 1) * 8;
    int b_col = ((lane >> 3) & 1) * 8;

    issue(0);
    for (int c = 0; c < GNC; c++) {
        CP_WAIT(0);
        __syncthreads();
        issue(c + 1);

        int s = c & 1;
        uint32_t Abase = sb + s * GSTAGE_B + (uint32_t)(wm * 32) * (GSAB * 2);
        uint32_t Bbase = sb + s * GSTAGE_B + GTILE_B + (uint32_t)(wn * 64) * (GSAB * 2);

#pragma unroll 1
        for (int sub = 0; sub < 2; sub++) {
            uint32_t kofs = (uint32_t)(sub * 32) * 2;
            // st-outer: 16 independent MMAs between any acc reuse
#pragma unroll
            for (int st = 0; st < 2; st++) {
                uint32_t a[2][4];
#pragma unroll
                for (int i = 0; i < 2; i++) {
                    uint32_t ad = Abase + (uint32_t)(i * 16 + a_row) * (GSAB * 2)
                                + kofs + (uint32_t)(st * 16 + a_col) * 2;
                    LDMX4(a[i][0], a[i][1], a[i][2], a[i][3], ad);
                }
                uint32_t b[4][4];
#pragma unroll
                for (int jp = 0; jp < 4; jp++) {
                    uint32_t bd = Bbase + (uint32_t)(jp * 16 + b_row) * (GSAB * 2)
                                + kofs + (uint32_t)(st * 16 + b_col) * 2;
                    LDMX4(b[jp][0], b[jp][1], b[jp][2], b[jp][3], bd);
                }
#pragma unroll
                for (int i = 0; i < 2; i++)
#pragma unroll
                    for (int j = 0; j < 8; j++) {
                        int jp = j >> 1, hf = (j & 1) * 2;
                        MMAE4M3(acc[i][j], a[i], b[jp][hf], b[jp][hf + 1]);
                    }
            }
        }
    }

    // epilogue: append positives to compact per-row lists (no dense store)
    int er = lane >> 2, ec = (lane & 3) * 2;
#pragma unroll
    for (int i = 0; i < 2; i++)
#pragma unroll
        for (int j = 0; j < 8; j++)
#pragma unroll
            for (int d = 0; d < 4; d++) {
                int r = row0 + wm * 32 + i * 16 + (d >> 1) * 8 + er;
                int cc = col0 + wn * 64 + j * 8 + ec + (d & 1);
                float d2 = fmaxf(g_sq[r] + g_sq[cc] - 2.0f * acc[i][j][d], 0.0f);
                if (d2 < D2_ZERO_CUT) {
                    float e = expf(-d2 / 9.0f);
                    if (e > 0.0f) {
                        int p = atomicAdd(&g_lcnt[r], 1);
                        g_lcols[(size_t)r * N + p] = cc;
                        g_lvals[(size_t)r * N + p] = e;
                        if (tr != tc) {
                            int p2 = atomicAdd(&g_lcnt[cc], 1);
                            g_lcols[(size_t)cc * N + p2] = r;
                            g_lvals[(size_t)cc * N + p2] = e;
                        }
                    }
                }
            }
}

// ---------------- support path: S = F @ W, bf16 split-2, 2-stage ------------
__device__ __forceinline__ void support_path(char* smem, int sid) {
    uint32_t sb = smem_u32(smem);
    int tid = threadIdx.x, wid = tid >> 5, lane = tid & 31;
    int row0 = (sid >> 3) * 128, col0 = (sid & 7) * 128;

    float acc[2][8][4];
#pragma unroll
    for (int i = 0; i < 2; i++)
#pragma unroll
        for (int j = 0; j < 8; j++)
#pragma unroll
            for (int d = 0; d < 4; d++) acc[i][j][d] = 0.0f;

    int ldr = tid >> 2, lds = tid & 3;

    auto issue = [&](int c) {
        if (c >= NC) return;
        int s = c & 1;
        uint32_t st = sb + s * SSTAGE_B;
        int k0 = c * KC;
#pragma unroll
        for (int h = 0; h < 2; h++) {
            int r = ldr + h * 64;
            uint32_t off = (uint32_t)r * (SAB * 2) + lds * 16;
            CP_ASYNC16(st + off,              (const void*)(g_Fbf + (size_t)(row0 + r) * D + k0 + lds * 8));
            CP_ASYNC16(st + TILE_B + off,     (const void*)(g_Flo + (size_t)(row0 + r) * D + k0 + lds * 8));
            CP_ASYNC16(st + 2 * TILE_B + off, (const void*)(g_Wth + (size_t)(col0 + r) * 1024 + k0 + lds * 8));
            CP_ASYNC16(st + 3 * TILE_B + off, (const void*)(g_Wtl + (size_t)(col0 + r) * 1024 + k0 + lds * 8));
        }
        CP_COMMIT();
    };

    int wm = wid & 3, wn = wid >> 2;
    int a_row = (lane & 7) + ((lane >> 3) & 1) * 8;
    int a_col = ((lane >> 4) & 1) * 8;
    int b_row = (lane & 7) + ((lane >> 4) & 1) * 8;
    int b_col = ((lane >> 3) & 1) * 8;

    issue(0);
    for (int c = 0; c < NC; c++) {
        CP_WAIT(0);
        __syncthreads();
        issue(c + 1);

        int s = c & 1;
        uint32_t Ahb = sb + s * SSTAGE_B + (uint32_t)(wm * 32) * (SAB * 2);
        uint32_t Alb = Ahb + TILE_B;
        uint32_t Bhb = sb + s * SSTAGE_B + 2 * TILE_B + (uint32_t)(wn * 64) * (SAB * 2);
        uint32_t Blb = Bhb + TILE_B;

        // st-outer; within st: term-major (16 independent MMAs per term)
#pragma unroll
        for (int st = 0; st < 2; st++) {
            uint32_t ah[2][4], al[2][4];
#pragma unroll
            for (int i = 0; i < 2; i++) {
                uint32_t ro = (uint32_t)(i * 16 + a_row) * (SAB * 2)
                            + (uint32_t)(st * 16 + a_col) * 2;
                LDMX4(ah[i][0], ah[i][1], ah[i][2], ah[i][3], Ahb + ro);
                LDMX4(al[i][0], al[i][1], al[i][2], al[i][3], Alb + ro);
            }
            uint32_t bh[4][4], bl[4][4];
#pragma unroll
            for (int jp = 0; jp < 4; jp++) {
                uint32_t ro = (uint32_t)(jp * 16 + b_row) * (SAB * 2)
                            + (uint32_t)(st * 16 + b_col) * 2;
                LDMX4(bh[jp][0], bh[jp][1], bh[jp][2], bh[jp][3], Bhb + ro);
                LDMX4(bl[jp][0], bl[jp][1], bl[jp][2], bl[jp][3], Blb + ro);
            }
            // term 0: hi * hi
#pragma unroll
            for (int i = 0; i < 2; i++)
#pragma unroll
                for (int j = 0; j < 8; j++) {
                    int jp = j >> 1, hf = (j & 1) * 2;
                    MMA16816(acc[i][j], ah[i], bh[jp][hf], bh[jp][hf + 1]);
                }
            // term 1: lo * hi
#pragma unroll
            for (int i = 0; i < 2; i++)
#pragma unroll
                for (int j = 0; j < 8; j++) {
                    int jp = j >> 1, hf = (j & 1) * 2;
                    MMA16816(acc[i][j], al[i], bh[jp][hf], bh[jp][hf + 1]);
                }
            // term 2: hi * lo
#pragma unroll
            for (int i = 0; i < 2; i++)
#pragma unroll
                for (int j = 0; j < 8; j++) {
                    int jp = j >> 1, hf = (j & 1) * 2;
                    MMA16816(acc[i][j], ah[i], bl[jp][hf], bl[jp][hf + 1]);
                }
        }
    }

    int er = lane >> 2, ec = (lane & 3) * 2;
#pragma unroll
    for (int i = 0; i < 2; i++)
#pragma unroll
        for (int j = 0; j < 8; j++)
#pragma unroll
            for (int dp = 0; dp < 2; dp++) {
                int r = row0 + wm * 32 + i * 16 + dp * 8 + er;
                int c = col0 + wn * 64 + j * 8 + ec;
                if (c < OUTD) {
                    float2 v = make_float2(acc[i][j][dp * 2], acc[i][j][dp * 2 + 1]);
                    *(float2*)(g_S + (size_t)r * OUTD + c) = v;
                }
            }
}

__global__ void __launch_bounds__(256, 2) dual_mma_kernel() {
    extern __shared__ char smem[];
    if (blockIdx.x < NSUP) support_path(smem, blockIdx.x);
    else                   gram_path(smem, blockIdx.x - NSUP);
}

// ---------------- per-row threshold: radix select over compact list ---------
__global__ void select_kernel() {
    int row = blockIdx.x;
    int L = g_lcnt[row];
    int tid = threadIdx.x, lane = tid & 31;
    if (L < KSEL) {               // K-th largest of the full row is a zero
        if (tid == 0) g_thr[row] = 0.0f;
        return;
    }
    __shared__ unsigned v[N];
    __shared__ int hist[256];
    __shared__ int sfx[256];
    __shared__ int s_bin, s_rem;
    for (int i = tid; i < L; i += 256)
        v[i] = __float_as_uint(g_lvals[(size_t)row * N + i]);
    __syncthreads();

    unsigned prefix = 0;
    int remaining = KSEL;
    for (int shift = 24; shift >= 0; shift -= 8) {
        hist[tid] = 0;
        __syncthreads();
        unsigned hm = (shift == 24) ? 0u : (0xFFFFFFFFu << (shift + 8));
        unsigned ph = prefix & hm;
        for (int i = tid; i < L; i += 256) {
            unsigned x = v[i];
            bool act = ((x & hm) == ph);
            int bin = (x >> shift) & 255;
            unsigned key = act ? (unsigned)bin : 0xFFFFFFFFu;
            unsigned mask = __match_any_sync(0xFFFFFFFFu, key);
            if (act && ((__ffs(mask) - 1) == lane))
                atomicAdd(&hist[bin], __popc(mask));
        }
        __syncthreads();
        sfx[tid] = hist[tid];
        __syncthreads();
        for (int off = 1; off < 256; off <<= 1) {
            int val = (tid + off < 256) ? sfx[tid + off] : 0;
            __syncthreads();
            sfx[tid] += val;
            __syncthreads();
        }
        int nb = (tid < 255) ? sfx[tid + 1] : 0;
        if (sfx[tid] >= remaining && nb < remaining) {
            s_bin = tid;
            s_rem = remaining - nb;
        }
        __syncthreads();
        prefix |= ((unsigned)s_bin) << shift;
        remaining = s_rem;
        __syncthreads();
    }
    if (tid == 0) g_thr[row] = __uint_as_float(prefix);
}

// ---------------- build mutual-kNN adjacency from compact lists -------------
__global__ void build_kernel() {
    int row = blockIdx.x, tid = threadIdx.x;
    int L = g_lcnt[row];
    if (L == 1) {                 // only the diagonal is positive
        if (tid == 0) { g_nnz[row] = 0; g_invd[row] = rsqrtf(2.0f); }
        return;
    }
    float ti = g_thr[row];
    __shared__ int s_n;
    __shared__ float red[256];
    if (tid == 0) s_n = 0;
    __syncthreads();
    float ls = 0.0f;
    for (int i = tid; i < L; i += 256) {
        int j = g_lcols[(size_t)row * N + i];
        float w = g_lvals[(size_t)row * N + i];
        if (j != row && w >= ti && w >= g_thr[j]) {
            int p = atomicAdd(&s_n, 1);
            g_cols2[(size_t)row * N + p] = j;
            g_vals2[(size_t)row * N + p] = w;
            ls += w;
        }
    }
    red[tid] = ls;
    __syncthreads();
    for (int o = 128; o > 0; o >>= 1) {
        if (tid < o) red[tid] += red[tid + o];
        __syncthreads();
    }
    if (tid == 0) {
        g_nnz[row] = s_n;
        g_invd[row] = rsqrtf(2.0f + red[0]);
    }
}

// ---------------- sparse propagation (scale fused on the fly) ---------------
__global__ void spmmA_kernel() {
    int row = blockIdx.x, tid = threadIdx.x;
    int nn = g_nnz[row];
    if (nn == 0) return;          // symmetric graph: nobody references this row
    float di = g_invd[row];
    float diag = di * di;
    const float* Xrow = g_S + (size_t)row * OUTD;
    int n0 = tid, n1 = tid + 256, n2 = tid + 512, n3 = tid + 768;
    float a0 = diag * Xrow[n0];
    float a1 = diag * Xrow[n1];
    float a2 = diag * Xrow[n2];
    float a3 = (n3 < OUTD) ? diag * Xrow[n3] : 0.0f;
    for (int e = 0; e < nn; e++) {
        int col = g_cols2[(size_t)row * N + e];
        float v = g_vals2[(size_t)row * N + e] * di * g_invd[col];
        const float* Xc = g_S + (size_t)col * OUTD;
        a0 += v * Xc[n0];
        a1 += v * Xc[n1];
        a2 += v * Xc[n2];
        if (n3 < OUTD) a3 += v * Xc[n3];
    }
    float* T = g_t1 + (size_t)row * OUTD;
    T[n0] = a0; T[n1] = a1; T[n2] = a2;
    if (n3 < OUTD) T[n3] = a3;
}

__global__ void spmmB_kernel(const float* __restrict__ bias,
                             const float* __restrict__ gamma,
                             const float* __restrict__ beta,
                             const float* __restrict__ mean,
                             const float* __restrict__ var,
                             const float* __restrict__ aifa1,
                             const float* __restrict__ aifa2,
                             const float* __restrict__ aifa3,
                             float* __restrict__ out) {
    int row = blockIdx.x, tid = threadIdx.x;
    int nn = g_nnz[row];
    float di = g_invd[row];
    float diag = di * di;
    float x0 = aifa1[0], x1 = aifa2[0], x2 = aifa3[0];
    float m = fmaxf(x0, fmaxf(x1, x2));
    float e0 = expf(x0 - m), e1 = expf(x1 - m), e2 = expf(x2 - m);
    float sden = e0 + e1 + e2;
    float c0 = e0 / sden, c1 = e1 / sden, c2 = e2 / sden;

    const float* Srow = g_S + (size_t)row * OUTD;
    float* Orow = out + (size_t)row * OUTD;

    if (nn == 0) {
#pragma unroll
        for (int q = 0; q < 4; q++) {
            int n = tid + q * 256;
            if (n < OUTD) {
                float s = Srow[n];
                float t = diag * s;
                float a = diag * t;
                float x = c0 * s + c1 * t + c2 * a + bias[n];
                float y = (x - mean[n]) * rsqrtf(var[n] + BN_EPS) * gamma[n] + beta[n];
                Orow[n] = fmaxf(y, 0.0f);
            }
        }
        return;
    }

    const float* Trow = g_t1 + (size_t)row * OUTD;
    int n0 = tid, n1 = tid + 256, n2 = tid + 512, n3 = tid + 768;
    float a0 = diag * Trow[n0];
    float a1 = diag * Trow[n1];
    float a2 = diag * Trow[n2];
    float a3 = (n3 < OUTD) ? diag * Trow[n3] : 0.0f;
    for (int e = 0; e < nn; e++) {
        int col = g_cols2[(size_t)row * N + e];
        float v = g_vals2[(size_t)row * N + e] * di * g_invd[col];
        const float* Xc = g_t1 + (size_t)col * OUTD;
        a0 += v * Xc[n0];
        a1 += v * Xc[n1];
        a2 += v * Xc[n2];
        if (n3 < OUTD) a3 += v * Xc[n3];
    }
    int ns[4] = {n0, n1, n2, n3};
    float as[4] = {a0, a1, a2, a3};
#pragma unroll
    for (int r = 0; r < 4; r++) {
        int n = ns[r];
        if (n < OUTD) {
            float x = c0 * Srow[n] + c1 * Trow[n] + c2 * as[r] + bias[n];
            float y = (x - mean[n]) * rsqrtf(var[n] + BN_EPS) * gamma[n] + beta[n];
            Orow[n] = fmaxf(y, 0.0f);
        }
    }
}

// ---------------- launch -----------------------------------------------------
extern "C" void kernel_launch(void* const* d_in, const int* in_sizes, int n_in,
                              void* d_out, int out_size) {
    const float* F     = (const float*)d_in[0];
    const float* W     = (const float*)d_in[1];
    const float* bias  = (const float*)d_in[2];
    const float* a1    = (const float*)d_in[3];
    const float* a2    = (const float*)d_in[4];
    const float* a3    = (const float*)d_in[5];
    const float* gamma = (const float*)d_in[6];
    const float* beta  = (const float*)d_in[7];
    const float* mean  = (const float*)d_in[8];
    const float* var   = (const float*)d_in[9];
    float* out = (float*)d_out;

    static int configured = -1;
    if (configured < 0) {
        cudaFuncSetAttribute(dual_mma_kernel,
                             cudaFuncAttributeMaxDynamicSharedMemorySize, DUAL_SMEM);
        configured = 1;
    }

    prep_F<<<N, 256>>>(F);
    prep_W<<<dim3(32, 32), dim3(32, 8)>>>(W);
    dual_mma_kernel<<<NSUP + 528, 256, DUAL_SMEM>>>();
    select_kernel<<<N, 256>>>();
    build_kernel<<<N, 256>>>();
    spmmA_kernel<<<N, 256>>>();
    spmmB_kernel<<<N, 256>>>(bias, gamma, beta, mean, var, a1, a2, a3, out);
}